// round 3
// baseline (speedup 1.0000x reference)
#include <cuda_runtime.h>

#define LEAKY 0.2f
#define BN_EPS 1e-5f
#define MAXN 50000
#define MAXE 1600000
#define MAXET (MAXN + MAXE)
#define SCAN_N 50176   /* 196*256, covers MAXN with zero padding */
#define NBLK 196

// ---------------- device scratch (static, allowed) ----------------
__device__ int   g_deg[SCAN_N];
__device__ int   g_off[MAXN + 1];
__device__ int   g_cursor[MAXN];
__device__ int   g_csr[MAXET];
__device__ int   g_bsum[256];
__device__ float g_red[128 * 256];
__device__ float g_scale[128];
__device__ float g_shift[128];
__device__ float g_Wcat[128 * 260];
__device__ float g_bcat[260];
__device__ float g_HW[MAXN * 128];
__device__ float g_HL[MAXN * 128];
__device__ float g_ESD[MAXN * 4];
__device__ float g_H[MAXN * 128];

// ---------------- CSR build ----------------
__global__ void k_zero_deg() {
    int i = blockIdx.x * 256 + threadIdx.x;
    if (i < SCAN_N) g_deg[i] = 0;
}

__global__ void k_count(const int* __restrict__ ei, int E, int ET) {
    int i = blockIdx.x * 256 + threadIdx.x;
    if (i < ET) {
        int d = (i < E) ? ei[E + i] : (i - E);
        atomicAdd(&g_deg[d], 1);
    }
}

__global__ void k_scan_bsum() {
    __shared__ int sh[256];
    int tid = threadIdx.x;
    sh[tid] = g_deg[blockIdx.x * 256 + tid];
    __syncthreads();
    for (int o = 128; o > 0; o >>= 1) {
        if (tid < o) sh[tid] += sh[tid + o];
        __syncthreads();
    }
    if (tid == 0) g_bsum[blockIdx.x] = sh[0];
}

__global__ void k_scan_top() {
    __shared__ int sh[256];
    int tid = threadIdx.x;
    int v = (tid < NBLK) ? g_bsum[tid] : 0;
    sh[tid] = v;
    __syncthreads();
    for (int o = 1; o < 256; o <<= 1) {
        int t = (tid >= o) ? sh[tid - o] : 0;
        __syncthreads();
        sh[tid] += t;
        __syncthreads();
    }
    g_bsum[tid] = sh[tid] - v;   // exclusive
}

__global__ void k_scan_off(int n) {
    __shared__ int sh[256];
    int tid = threadIdx.x;
    int gi = blockIdx.x * 256 + tid;
    int v = g_deg[gi];
    sh[tid] = v;
    __syncthreads();
    for (int o = 1; o < 256; o <<= 1) {
        int t = (tid >= o) ? sh[tid - o] : 0;
        __syncthreads();
        sh[tid] += t;
        __syncthreads();
    }
    int ex = sh[tid] - v + g_bsum[blockIdx.x];
    if (gi <= n) g_off[gi] = ex;
    if (gi < n)  g_cursor[gi] = ex;
}

__global__ void k_scatter(const int* __restrict__ ei, int E, int ET) {
    int i = blockIdx.x * 256 + threadIdx.x;
    if (i < ET) {
        int s, d;
        if (i < E) { s = ei[i]; d = ei[E + i]; }
        else       { s = d = i - E; }
        int pos = atomicAdd(&g_cursor[d], 1);
        g_csr[pos] = s;
    }
}

// ---------------- BatchNorm stats (deterministic tree reduce) ----------------
// A == nullptr means "read from g_H"
__global__ __launch_bounds__(256) void k_bn_reduce(const float* __restrict__ A, int total) {
    const float* H = A ? A : g_H;
    __shared__ float ss[256], sq[256];
    int tid = threadIdx.x;
    float s = 0.f, q = 0.f;
    for (int e = blockIdx.x * 256 + tid; e < total; e += gridDim.x * 256) {
        float v = H[e];
        s += v; q += v * v;
    }
    ss[tid] = s; sq[tid] = q;
    __syncthreads();
    if (tid < 128) {
        g_red[blockIdx.x * 256 + tid]       = ss[tid] + ss[tid + 128];
        g_red[blockIdx.x * 256 + 128 + tid] = sq[tid] + sq[tid + 128];
    }
}

__global__ void k_bn_final(const float* __restrict__ bg, const float* __restrict__ bb, float inv_n) {
    int c = threadIdx.x;  // 128
    float s = 0.f, q = 0.f;
    for (int b = 0; b < 128; b++) {
        s += g_red[b * 256 + c];
        q += g_red[b * 256 + 128 + c];
    }
    float mu  = s * inv_n;
    float var = q * inv_n - mu * mu;
    float sc  = bg[c] * rsqrtf(var + BN_EPS);
    g_scale[c] = sc;
    g_shift[c] = bb[c] - mu * sc;
}

// ---------------- weight concat:  [W(128) | lw(128) | W@a_src(2) | W@a_dst(2)] ----------------
__global__ void k_prep_w12(const float* __restrict__ W, const float* __restrict__ lw,
                           const float* __restrict__ lb, const float* __restrict__ as,
                           const float* __restrict__ ad) {
    int idx = blockIdx.x * 256 + threadIdx.x;  // 128*260
    if (idx >= 128 * 260) return;
    int k = idx / 260, j = idx % 260;
    float v;
    if (j < 128)       v = W[k * 128 + j];
    else if (j < 256)  v = lw[k * 128 + (j - 128)];
    else {
        int t = j - 256;           // 0:es_h0 1:es_h1 2:ed_h0 3:ed_h1
        int hh = t & 1;
        const float* a = (t < 2) ? as : ad;
        float s = 0.f;
        for (int f = 0; f < 64; f++) s += W[k * 128 + hh * 64 + f] * a[hh * 64 + f];
        v = s;
    }
    g_Wcat[idx] = v;
    if (k == 0) g_bcat[j] = (j >= 128 && j < 256) ? lb[j - 128] : 0.f;
}

__global__ void k_prep_w3(const float* __restrict__ W3, const float* __restrict__ lw3,
                          const float* __restrict__ lb3, const float* __restrict__ as3,
                          const float* __restrict__ ad3) {
    int idx = blockIdx.x * 256 + threadIdx.x;  // 128*6
    if (idx >= 128 * 6) return;
    int k = idx / 6, j = idx % 6;
    float v;
    if (j < 2)      v = W3[k * 2 + j];
    else if (j < 4) v = lw3[k * 2 + (j - 2)];
    else {
        const float* a = (j == 4) ? as3 : ad3;
        v = W3[k * 2] * a[0] + W3[k * 2 + 1] * a[1];
    }
    g_Wcat[idx] = v;
    if (k == 0) g_bcat[j] = (j == 2 || j == 3) ? lb3[j - 2] : 0.f;
}

// ---------------- GEMM: C[M,260] = bn(A)[M,128] @ Wcat[128,260] + bcat ----------------
__global__ __launch_bounds__(256) void k_gemm_bn(const float* __restrict__ Ain, int M) {
    const float* A = Ain ? Ain : g_H;
    const int NC = 260;
    __shared__ float As[16][64];
    __shared__ float Bs[16][64];
    int m0 = blockIdx.x * 64, n0 = blockIdx.y * 64;
    int tid = threadIdx.x;
    int tx = tid & 15, ty = tid >> 4;
    float acc[4][4] = {};
    for (int k0 = 0; k0 < 128; k0 += 16) {
#pragma unroll
        for (int p = 0; p < 4; p++) {
            int e = p * 256 + tid;
            int m = e >> 4, k = e & 15;
            int gm = m0 + m, gk = k0 + k;
            As[k][m] = (gm < M) ? (A[gm * 128 + gk] * g_scale[gk] + g_shift[gk]) : 0.f;
        }
#pragma unroll
        for (int p = 0; p < 4; p++) {
            int e = p * 256 + tid;
            int k = e >> 6, nn = e & 63;
            int gn = n0 + nn;
            Bs[k][nn] = (gn < NC) ? g_Wcat[(k0 + k) * NC + gn] : 0.f;
        }
        __syncthreads();
#pragma unroll
        for (int kk = 0; kk < 16; kk++) {
            float4 a4 = *(const float4*)&As[kk][ty * 4];
            float4 b4 = *(const float4*)&Bs[kk][tx * 4];
            float aa[4] = {a4.x, a4.y, a4.z, a4.w};
            float bb[4] = {b4.x, b4.y, b4.z, b4.w};
#pragma unroll
            for (int i = 0; i < 4; i++)
#pragma unroll
                for (int j = 0; j < 4; j++) acc[i][j] += aa[i] * bb[j];
        }
        __syncthreads();
    }
#pragma unroll
    for (int i = 0; i < 4; i++) {
        int gm = m0 + ty * 4 + i;
        if (gm >= M) continue;
#pragma unroll
        for (int j = 0; j < 4; j++) {
            int gn = n0 + tx * 4 + j;
            if (gn >= NC) continue;
            float v = acc[i][j] + g_bcat[gn];
            if (gn < 128)      g_HW[gm * 128 + gn] = v;
            else if (gn < 256) g_HL[gm * 128 + gn - 128] = v;
            else               g_ESD[gm * 4 + (gn - 256)] = v;
        }
    }
}

// ---------------- skinny GEMV for layer 3: 6 cols ----------------
__global__ __launch_bounds__(256) void k_gemv6(int n) {
    const float* A = g_H;
    __shared__ float ws[128 * 6];
    __shared__ float bs[6];
    int tid = threadIdx.x;
    for (int i = tid; i < 768; i += 256) ws[i] = g_Wcat[i];
    if (tid < 6) bs[tid] = g_bcat[tid];
    __syncthreads();
    int row = blockIdx.x * 8 + (tid >> 5);
    int lane = tid & 31;
    if (row >= n) return;
    float4 a = ((const float4*)A)[row * 32 + lane];
    int k = lane * 4;
    float a0 = a.x * g_scale[k]     + g_shift[k];
    float a1 = a.y * g_scale[k + 1] + g_shift[k + 1];
    float a2 = a.z * g_scale[k + 2] + g_shift[k + 2];
    float a3 = a.w * g_scale[k + 3] + g_shift[k + 3];
    float c[6];
#pragma unroll
    for (int j = 0; j < 6; j++)
        c[j] = a0 * ws[k * 6 + j] + a1 * ws[(k + 1) * 6 + j] +
               a2 * ws[(k + 2) * 6 + j] + a3 * ws[(k + 3) * 6 + j];
#pragma unroll
    for (int j = 0; j < 6; j++)
#pragma unroll
        for (int o = 16; o > 0; o >>= 1) c[j] += __shfl_xor_sync(0xffffffffu, c[j], o);
    if (lane == 0) {
        g_HW[row * 2]     = c[0];
        g_HW[row * 2 + 1] = c[1];
        g_HL[row * 2]     = c[2] + bs[2];
        g_HL[row * 2 + 1] = c[3] + bs[3];
        g_ESD[row * 2]     = c[4];
        g_ESD[row * 2 + 1] = c[5];
    }
}

// ---------------- GAT edge phase, layers 1/2 (H=2,F=64): warp per dst node ----------------
__device__ __forceinline__ float leaky(float x) { return (x > 0.f) ? x : LEAKY * x; }

__global__ __launch_bounds__(256) void k_gat_edge12(const float* __restrict__ gb, int n) {
    int warp = (blockIdx.x * 256 + threadIdx.x) >> 5;
    int lane = threadIdx.x & 31;
    if (warp >= n) return;
    int node = warp;
    int beg = g_off[node], end = g_off[node + 1];
    float ed0 = g_ESD[node * 4 + 2], ed1 = g_ESD[node * 4 + 3];

    // pass 1: segment max per head
    float m0 = -1e30f, m1 = -1e30f;
    for (int i = beg + lane; i < end; i += 32) {
        int s = g_csr[i];
        m0 = fmaxf(m0, leaky(g_ESD[s * 4]     + ed0));
        m1 = fmaxf(m1, leaky(g_ESD[s * 4 + 1] + ed1));
    }
#pragma unroll
    for (int o = 16; o > 0; o >>= 1) {
        m0 = fmaxf(m0, __shfl_xor_sync(0xffffffffu, m0, o));
        m1 = fmaxf(m1, __shfl_xor_sync(0xffffffffu, m1, o));
    }

    // pass 2: exp + weighted aggregation
    float sum0 = 0.f, sum1 = 0.f;
    float ax = 0.f, ay = 0.f, az = 0.f, aw = 0.f;
    const float4* HW4 = (const float4*)g_HW;
    for (int base = beg; base < end; base += 32) {
        int i = base + lane;
        int s = 0;
        float p0 = 0.f, p1 = 0.f;
        if (i < end) {
            s = g_csr[i];
            p0 = __expf(leaky(g_ESD[s * 4]     + ed0) - m0);
            p1 = __expf(leaky(g_ESD[s * 4 + 1] + ed1) - m1);
        }
        sum0 += p0; sum1 += p1;
        int cnt = min(32, end - base);
        if (cnt == 32) {
#pragma unroll
            for (int j = 0; j < 32; j++) {
                int sj   = __shfl_sync(0xffffffffu, s, j);
                float q0 = __shfl_sync(0xffffffffu, p0, j);
                float q1 = __shfl_sync(0xffffffffu, p1, j);
                float ph = (lane < 16) ? q0 : q1;
                float4 hv = HW4[sj * 32 + lane];
                ax += ph * hv.x; ay += ph * hv.y; az += ph * hv.z; aw += ph * hv.w;
            }
        } else {
            for (int j = 0; j < cnt; j++) {
                int sj   = __shfl_sync(0xffffffffu, s, j);
                float q0 = __shfl_sync(0xffffffffu, p0, j);
                float q1 = __shfl_sync(0xffffffffu, p1, j);
                float ph = (lane < 16) ? q0 : q1;
                float4 hv = HW4[sj * 32 + lane];
                ax += ph * hv.x; ay += ph * hv.y; az += ph * hv.z; aw += ph * hv.w;
            }
        }
    }
#pragma unroll
    for (int o = 16; o > 0; o >>= 1) {
        sum0 += __shfl_xor_sync(0xffffffffu, sum0, o);
        sum1 += __shfl_xor_sync(0xffffffffu, sum1, o);
    }
    float inv = 1.f / ((lane < 16) ? sum0 : sum1);

    // combine: relu(lin + lb + gat + gb)
    float4 hl = ((const float4*)g_HL)[node * 32 + lane];
    float4 gv = ((const float4*)gb)[lane];
    float4 o4;
    o4.x = fmaxf(hl.x + gv.x + ax * inv, 0.f);
    o4.y = fmaxf(hl.y + gv.y + ay * inv, 0.f);
    o4.z = fmaxf(hl.z + gv.z + az * inv, 0.f);
    o4.w = fmaxf(hl.w + gv.w + aw * inv, 0.f);
    ((float4*)g_H)[node * 32 + lane] = o4;
}

// ---------------- GAT edge phase, layer 3 (H=1,F=2): warp per dst node ----------------
__global__ __launch_bounds__(256) void k_gat_edge3(const float* __restrict__ gb3,
                                                   float* __restrict__ out, int n) {
    int warp = (blockIdx.x * 256 + threadIdx.x) >> 5;
    int lane = threadIdx.x & 31;
    if (warp >= n) return;
    int node = warp;
    int beg = g_off[node], end = g_off[node + 1];
    float edv = g_ESD[node * 2 + 1];

    float m = -1e30f;
    for (int i = beg + lane; i < end; i += 32) {
        int s = g_csr[i];
        m = fmaxf(m, leaky(g_ESD[s * 2] + edv));
    }
#pragma unroll
    for (int o = 16; o > 0; o >>= 1) m = fmaxf(m, __shfl_xor_sync(0xffffffffu, m, o));

    float sum = 0.f, a0 = 0.f, a1 = 0.f;
    for (int i = beg + lane; i < end; i += 32) {
        int s = g_csr[i];
        float p = __expf(leaky(g_ESD[s * 2] + edv) - m);
        sum += p;
        a0 += p * g_HW[s * 2];
        a1 += p * g_HW[s * 2 + 1];
    }
#pragma unroll
    for (int o = 16; o > 0; o >>= 1) {
        sum += __shfl_xor_sync(0xffffffffu, sum, o);
        a0  += __shfl_xor_sync(0xffffffffu, a0, o);
        a1  += __shfl_xor_sync(0xffffffffu, a1, o);
    }
    if (lane == 0) {
        float inv = 1.f / sum;
        out[node * 2]     = fmaxf(g_HL[node * 2]     + gb3[0] + a0 * inv, 0.f);
        out[node * 2 + 1] = fmaxf(g_HL[node * 2 + 1] + gb3[1] + a1 * inv, 0.f);
    }
}

// ---------------- host launch ----------------
extern "C" void kernel_launch(void* const* d_in, const int* in_sizes, int n_in,
                              void* d_out, int out_size) {
    const float* x  = (const float*)d_in[0];
    const int*   ei = (const int*)d_in[1];   // int32! (jax x64 disabled)
    const float *W1 = (const float*)d_in[2],  *as1 = (const float*)d_in[3],
                *ad1 = (const float*)d_in[4], *gb1 = (const float*)d_in[5],
                *lw1 = (const float*)d_in[6], *lb1 = (const float*)d_in[7],
                *bg1 = (const float*)d_in[8], *bb1 = (const float*)d_in[9];
    const float *W2 = (const float*)d_in[10], *as2 = (const float*)d_in[11],
                *ad2 = (const float*)d_in[12], *gb2 = (const float*)d_in[13],
                *lw2 = (const float*)d_in[14], *lb2 = (const float*)d_in[15],
                *bg2 = (const float*)d_in[16], *bb2 = (const float*)d_in[17];
    const float *W3 = (const float*)d_in[18], *as3 = (const float*)d_in[19],
                *ad3 = (const float*)d_in[20], *gb3 = (const float*)d_in[21],
                *lw3 = (const float*)d_in[22], *lb3 = (const float*)d_in[23],
                *bg3 = (const float*)d_in[24], *bb3 = (const float*)d_in[25];
    (void)n_in; (void)out_size;

    int n  = in_sizes[0] / 128;
    int E  = in_sizes[1] / 2;
    int ET = E + n;
    float* out = (float*)d_out;

    int eb = (ET + 255) / 256;
    dim3 gg((n + 63) / 64, 5);
    int wb = (n + 7) / 8;
    float inv_n = 1.f / (float)n;

    // ---- CSR build (once; shared by all 3 layers) ----
    k_zero_deg<<<(SCAN_N + 255) / 256, 256>>>();
    k_count<<<eb, 256>>>(ei, E, ET);
    k_scan_bsum<<<NBLK, 256>>>();
    k_scan_top<<<1, 256>>>();
    k_scan_off<<<NBLK, 256>>>(n);
    k_scatter<<<eb, 256>>>(ei, E, ET);

    // ---- layer 1 ----
    k_bn_reduce<<<128, 256>>>(x, n * 128);
    k_bn_final<<<1, 128>>>(bg1, bb1, inv_n);
    k_prep_w12<<<(128 * 260 + 255) / 256, 256>>>(W1, lw1, lb1, as1, ad1);
    k_gemm_bn<<<gg, 256>>>(x, n);
    k_gat_edge12<<<wb, 256>>>(gb1, n);

    // ---- layer 2 ----
    k_bn_reduce<<<128, 256>>>(nullptr, n * 128);
    k_bn_final<<<1, 128>>>(bg2, bb2, inv_n);
    k_prep_w12<<<(128 * 260 + 255) / 256, 256>>>(W2, lw2, lb2, as2, ad2);
    k_gemm_bn<<<gg, 256>>>(nullptr, n);
    k_gat_edge12<<<wb, 256>>>(gb2, n);

    // ---- layer 3 ----
    k_bn_reduce<<<128, 256>>>(nullptr, n * 128);
    k_bn_final<<<1, 128>>>(bg3, bb3, inv_n);
    k_prep_w3<<<3, 256>>>(W3, lw3, lb3, as3, ad3);
    k_gemv6<<<wb, 256>>>(n);
    k_gat_edge3<<<wb, 256>>>(gb3, out, n);
}

// round 5
// speedup vs baseline: 1.2557x; 1.2557x over previous
#include <cuda_runtime.h>
#include <cuda_bf16.h>
#include <cstdint>

#define LEAKY 0.2f
#define BN_EPS 1e-5f
#define MAXN 50000
#define MAXE 1600000
#define MAXET (MAXN + MAXE)
#define SCAN_N 50176
#define NBLK 196

// ---------------- device scratch ----------------
__device__ int   g_deg[SCAN_N];
__device__ int   g_off[MAXN + 1];
__device__ int   g_cursor[MAXN];
__device__ int   g_csr[MAXET];
__device__ int   g_bsum[256];
__device__ float g_red[128 * 256];
__device__ float g_scale[128];
__device__ float g_shift[128];
__device__ float g_Wcat[128 * 260];
__device__ float g_bcat[260];
__device__ float g_HW[MAXN * 128];
__device__ float g_HL[MAXN * 128];
__device__ float g_ESD[MAXN * 4];
__device__ float g_H[MAXN * 128];
__device__ __nv_bfloat16 g_Bhi[256 * 128];   // [n][k]
__device__ __nv_bfloat16 g_Blo[256 * 128];

// ---------------- CSR build ----------------
__global__ void k_zero_deg() {
    int i = blockIdx.x * 256 + threadIdx.x;
    if (i < SCAN_N) g_deg[i] = 0;
}
__global__ void k_count(const int* __restrict__ ei, int E, int ET) {
    int i = blockIdx.x * 256 + threadIdx.x;
    if (i < ET) {
        int d = (i < E) ? ei[E + i] : (i - E);
        atomicAdd(&g_deg[d], 1);
    }
}
__global__ void k_scan_bsum() {
    __shared__ int sh[256];
    int tid = threadIdx.x;
    sh[tid] = g_deg[blockIdx.x * 256 + tid];
    __syncthreads();
    for (int o = 128; o > 0; o >>= 1) {
        if (tid < o) sh[tid] += sh[tid + o];
        __syncthreads();
    }
    if (tid == 0) g_bsum[blockIdx.x] = sh[0];
}
__global__ void k_scan_top() {
    __shared__ int sh[256];
    int tid = threadIdx.x;
    int v = (tid < NBLK) ? g_bsum[tid] : 0;
    sh[tid] = v;
    __syncthreads();
    for (int o = 1; o < 256; o <<= 1) {
        int t = (tid >= o) ? sh[tid - o] : 0;
        __syncthreads();
        sh[tid] += t;
        __syncthreads();
    }
    g_bsum[tid] = sh[tid] - v;
}
__global__ void k_scan_off(int n) {
    __shared__ int sh[256];
    int tid = threadIdx.x;
    int gi = blockIdx.x * 256 + tid;
    int v = g_deg[gi];
    sh[tid] = v;
    __syncthreads();
    for (int o = 1; o < 256; o <<= 1) {
        int t = (tid >= o) ? sh[tid - o] : 0;
        __syncthreads();
        sh[tid] += t;
        __syncthreads();
    }
    int ex = sh[tid] - v + g_bsum[blockIdx.x];
    if (gi <= n) g_off[gi] = ex;
    if (gi < n)  g_cursor[gi] = ex;
}
__global__ void k_scatter(const int* __restrict__ ei, int E, int ET) {
    int i = blockIdx.x * 256 + threadIdx.x;
    if (i < ET) {
        int s, d;
        if (i < E) { s = ei[i]; d = ei[E + i]; }
        else       { s = d = i - E; }
        int pos = atomicAdd(&g_cursor[d], 1);
        g_csr[pos] = s;
    }
}

// ---------------- BatchNorm stats ----------------
__global__ __launch_bounds__(256) void k_bn_reduce(const float* __restrict__ A, int total) {
    const float* H = A ? A : g_H;
    __shared__ float ss[256], sq[256];
    int tid = threadIdx.x;
    float s = 0.f, q = 0.f;
    for (int e = blockIdx.x * 256 + tid; e < total; e += gridDim.x * 256) {
        float v = H[e];
        s += v; q += v * v;
    }
    ss[tid] = s; sq[tid] = q;
    __syncthreads();
    if (tid < 128) {
        g_red[blockIdx.x * 256 + tid]       = ss[tid] + ss[tid + 128];
        g_red[blockIdx.x * 256 + 128 + tid] = sq[tid] + sq[tid + 128];
    }
}
__global__ void k_bn_final(const float* __restrict__ bg, const float* __restrict__ bb, float inv_n) {
    int c = threadIdx.x;
    float s = 0.f, q = 0.f;
    for (int b = 0; b < 128; b++) {
        s += g_red[b * 256 + c];
        q += g_red[b * 256 + 128 + c];
    }
    float mu  = s * inv_n;
    float var = q * inv_n - mu * mu;
    float sc  = bg[c] * rsqrtf(var + BN_EPS);
    g_scale[c] = sc;
    g_shift[c] = bb[c] - mu * sc;
}

// ---------------- weight prep ----------------
__global__ void k_prep_w12(const float* __restrict__ W, const float* __restrict__ lw,
                           const float* __restrict__ lb, const float* __restrict__ as,
                           const float* __restrict__ ad) {
    int idx = blockIdx.x * 256 + threadIdx.x;
    if (idx >= 128 * 260) return;
    int k = idx / 260, j = idx % 260;
    float v;
    if (j < 128)       v = W[k * 128 + j];
    else if (j < 256)  v = lw[k * 128 + (j - 128)];
    else {
        int t = j - 256;
        int hh = t & 1;
        const float* a = (t < 2) ? as : ad;
        float s = 0.f;
        for (int f = 0; f < 64; f++) s += W[k * 128 + hh * 64 + f] * a[hh * 64 + f];
        v = s;
    }
    g_Wcat[idx] = v;
    if (k == 0) g_bcat[j] = (j >= 128 && j < 256) ? lb[j - 128] : 0.f;
}
__global__ void k_prep_b() {
    int idx = blockIdx.x * 256 + threadIdx.x;   // 256 n * 128 k
    if (idx >= 256 * 128) return;
    int nn = idx >> 7, k = idx & 127;
    float v = g_Wcat[k * 260 + nn];
    __nv_bfloat16 h = __float2bfloat16(v);
    g_Bhi[idx] = h;
    g_Blo[idx] = __float2bfloat16(v - __bfloat162float(h));
}
__global__ void k_prep_w3(const float* __restrict__ W3, const float* __restrict__ lw3,
                          const float* __restrict__ lb3, const float* __restrict__ as3,
                          const float* __restrict__ ad3) {
    int idx = blockIdx.x * 256 + threadIdx.x;
    if (idx >= 128 * 6) return;
    int k = idx / 6, j = idx % 6;
    float v;
    if (j < 2)      v = W3[k * 2 + j];
    else if (j < 4) v = lw3[k * 2 + (j - 2)];
    else {
        const float* a = (j == 4) ? as3 : ad3;
        v = W3[k * 2] * a[0] + W3[k * 2 + 1] * a[1];
    }
    g_Wcat[idx] = v;
    if (k == 0) g_bcat[j] = (j == 2 || j == 3) ? lb3[j - 2] : 0.f;
}

// ---------------- mma.sync GEMM helpers ----------------
__device__ __forceinline__ uint32_t smem_u32(const void* p) {
    uint32_t a;
    asm("{ .reg .u64 t; cvta.to.shared.u64 t, %1; cvt.u32.u64 %0, t; }" : "=r"(a) : "l"(p));
    return a;
}
__device__ __forceinline__ void ldsm_x4(uint32_t* r, uint32_t addr) {
    asm volatile("ldmatrix.sync.aligned.m8n8.x4.shared.b16 {%0,%1,%2,%3}, [%4];"
        : "=r"(r[0]), "=r"(r[1]), "=r"(r[2]), "=r"(r[3]) : "r"(addr));
}
__device__ __forceinline__ void ldsm_x2(uint32_t* r, uint32_t addr) {
    asm volatile("ldmatrix.sync.aligned.m8n8.x2.shared.b16 {%0,%1}, [%2];"
        : "=r"(r[0]), "=r"(r[1]) : "r"(addr));
}
__device__ __forceinline__ void mma_bf16(float* d, const uint32_t* a, const uint32_t* b) {
    asm volatile("mma.sync.aligned.m16n8k16.row.col.f32.bf16.bf16.f32 "
        "{%0,%1,%2,%3}, {%4,%5,%6,%7}, {%8,%9}, {%0,%1,%2,%3};"
        : "+f"(d[0]), "+f"(d[1]), "+f"(d[2]), "+f"(d[3])
        : "r"(a[0]), "r"(a[1]), "r"(a[2]), "r"(a[3]), "r"(b[0]), "r"(b[1]));
}

// ---------------- tensor-core GEMM: C[M,256] = bn(A)[M,128] @ Wcat[:, :256] ----------------
// bf16x3 split (hi*hi + hi*lo + lo*hi) in fp32 accum via mma.sync m16n8k16.
#define APAD 136                       /* bf16 elems per smem row (272 B) */
#define TILE_BYTES (128 * APAD * 2)    /* 34816 */
#define GEMM_SMEM  (4 * TILE_BYTES)    /* 139264 */

__global__ __launch_bounds__(256, 1) void k_gemm_mma(const float* __restrict__ Ain, int M) {
    const float* A = Ain ? Ain : g_H;
    extern __shared__ char sm[];
    __nv_bfloat16* sAhi = (__nv_bfloat16*)sm;
    __nv_bfloat16* sAlo = (__nv_bfloat16*)(sm + TILE_BYTES);
    __nv_bfloat16* sBhi = (__nv_bfloat16*)(sm + 2 * TILE_BYTES);
    __nv_bfloat16* sBlo = (__nv_bfloat16*)(sm + 3 * TILE_BYTES);

    int tid = threadIdx.x, lane = tid & 31, wid = tid >> 5;
    int warp_m = wid & 1;          // 2 warps over M (64 rows each)
    int warp_n = wid >> 1;         // 4 warps over N (32 cols each)
    int m0 = blockIdx.x * 128;
    int n0 = blockIdx.y * 128;     // 0 -> g_HW cols, 1 -> g_HL cols

    // ---- stage A (bn + hi/lo split) ----
    for (int idx = tid; idx < 4096; idx += 256) {
        int row = idx >> 5, c = (idx & 31) * 4;
        int gm = m0 + row;
        float4 t = (gm < M) ? *(const float4*)(A + gm * 128 + c)
                            : make_float4(0.f, 0.f, 0.f, 0.f);
        float v0 = t.x * g_scale[c]     + g_shift[c];
        float v1 = t.y * g_scale[c + 1] + g_shift[c + 1];
        float v2 = t.z * g_scale[c + 2] + g_shift[c + 2];
        float v3 = t.w * g_scale[c + 3] + g_shift[c + 3];
        if (gm >= M) { v0 = v1 = v2 = v3 = 0.f; }
        __nv_bfloat16 h0 = __float2bfloat16(v0), h1 = __float2bfloat16(v1);
        __nv_bfloat16 h2 = __float2bfloat16(v2), h3 = __float2bfloat16(v3);
        __nv_bfloat162 hp0(h0, h1), hp1(h2, h3);
        __nv_bfloat162 lp0(__float2bfloat16(v0 - __bfloat162float(h0)),
                           __float2bfloat16(v1 - __bfloat162float(h1)));
        __nv_bfloat162 lp1(__float2bfloat16(v2 - __bfloat162float(h2)),
                           __float2bfloat16(v3 - __bfloat162float(h3)));
        int o = row * APAD + c;
        *(__nv_bfloat162*)(sAhi + o)     = hp0;
        *(__nv_bfloat162*)(sAhi + o + 2) = hp1;
        *(__nv_bfloat162*)(sAlo + o)     = lp0;
        *(__nv_bfloat162*)(sAlo + o + 2) = lp1;
    }
    // ---- stage B (pre-split, [n][k]) ----
    for (int idx = tid; idx < 2048; idx += 256) {
        int row = idx >> 4, c = (idx & 15) * 8;
        int gn = n0 + row;
        uint4 hv = *(const uint4*)(g_Bhi + gn * 128 + c);
        uint4 lv = *(const uint4*)(g_Blo + gn * 128 + c);
        int o = row * APAD + c;
        *(uint4*)(sBhi + o) = hv;
        *(uint4*)(sBlo + o) = lv;
    }
    __syncthreads();

    // ---- ldmatrix base addresses ----
    int rA = lane & 15, cA = (lane >> 4) * 8;          // x4: 16 row addrs, 2 k-halves
    int rB = lane & 7,  cB = ((lane >> 3) & 1) * 8;    // x2: 8 row addrs,  2 k-halves
    uint32_t baseAhi[4], baseAlo[4], baseBhi[4], baseBlo[4];
#pragma unroll
    for (int mt = 0; mt < 4; mt++) {
        int row = warp_m * 64 + mt * 16 + rA;
        baseAhi[mt] = smem_u32(sAhi + row * APAD + cA);
        baseAlo[mt] = smem_u32(sAlo + row * APAD + cA);
    }
#pragma unroll
    for (int nt = 0; nt < 4; nt++) {
        int row = warp_n * 32 + nt * 8 + rB;
        baseBhi[nt] = smem_u32(sBhi + row * APAD + cB);
        baseBlo[nt] = smem_u32(sBlo + row * APAD + cB);
    }

    float acc[4][4][4] = {};
#pragma unroll
    for (int ks = 0; ks < 8; ks++) {
        uint32_t koff = ks * 32;   // 16 bf16 = 32 bytes
        uint32_t ahi[4][4], alo[4][4], bhi[4][2], blo[4][2];
#pragma unroll
        for (int mt = 0; mt < 4; mt++) {
            ldsm_x4(ahi[mt], baseAhi[mt] + koff);
            ldsm_x4(alo[mt], baseAlo[mt] + koff);
        }
#pragma unroll
        for (int nt = 0; nt < 4; nt++) {
            ldsm_x2(bhi[nt], baseBhi[nt] + koff);
            ldsm_x2(blo[nt], baseBlo[nt] + koff);
        }
#pragma unroll
        for (int mt = 0; mt < 4; mt++)
#pragma unroll
            for (int nt = 0; nt < 4; nt++) {
                mma_bf16(acc[mt][nt], ahi[mt], bhi[nt]);
                mma_bf16(acc[mt][nt], ahi[mt], blo[nt]);
                mma_bf16(acc[mt][nt], alo[mt], bhi[nt]);
            }
    }

    // ---- epilogue: bias + scatter to g_HW / g_HL ----
    float* dst = (blockIdx.y == 0) ? g_HW : g_HL;
#pragma unroll
    for (int mt = 0; mt < 4; mt++) {
        int gm0 = m0 + warp_m * 64 + mt * 16 + (lane >> 2);
#pragma unroll
        for (int nt = 0; nt < 4; nt++) {
            int col = warp_n * 32 + nt * 8 + (lane & 3) * 2;
            float b0 = g_bcat[n0 + col], b1 = g_bcat[n0 + col + 1];
            if (gm0 < M) {
                float2 v = {acc[mt][nt][0] + b0, acc[mt][nt][1] + b1};
                *(float2*)(dst + gm0 * 128 + col) = v;
            }
            if (gm0 + 8 < M) {
                float2 v = {acc[mt][nt][2] + b0, acc[mt][nt][3] + b1};
                *(float2*)(dst + (gm0 + 8) * 128 + col) = v;
            }
        }
    }
}

// ---------------- attention columns (es0,es1,ed0,ed1): warp per node ----------------
__global__ __launch_bounds__(256) void k_esd(const float* __restrict__ Ain, int n) {
    const float* A = Ain ? Ain : g_H;
    __shared__ float w[512];   // [k][4]
    int tid = threadIdx.x;
    for (int i = tid; i < 512; i += 256)
        w[i] = g_Wcat[(i >> 2) * 260 + 256 + (i & 3)];
    __syncthreads();
    int node = blockIdx.x * 8 + (tid >> 5);
    int lane = tid & 31;
    if (node >= n) return;
    float4 a = ((const float4*)A)[node * 32 + lane];
    int k = lane * 4;
    float a0 = a.x * g_scale[k]     + g_shift[k];
    float a1 = a.y * g_scale[k + 1] + g_shift[k + 1];
    float a2 = a.z * g_scale[k + 2] + g_shift[k + 2];
    float a3 = a.w * g_scale[k + 3] + g_shift[k + 3];
    float s[4];
#pragma unroll
    for (int t = 0; t < 4; t++)
        s[t] = a0 * w[k * 4 + t] + a1 * w[(k + 1) * 4 + t] +
               a2 * w[(k + 2) * 4 + t] + a3 * w[(k + 3) * 4 + t];
#pragma unroll
    for (int t = 0; t < 4; t++)
#pragma unroll
        for (int o = 16; o > 0; o >>= 1) s[t] += __shfl_xor_sync(0xffffffffu, s[t], o);
    if (lane == 0) {
        float4 o4 = {s[0], s[1], s[2], s[3]};
        ((float4*)g_ESD)[node] = o4;
    }
}

// ---------------- skinny GEMV for layer 3 ----------------
__global__ __launch_bounds__(256) void k_gemv6(int n) {
    const float* A = g_H;
    __shared__ float ws[128 * 6];
    __shared__ float bs[6];
    int tid = threadIdx.x;
    for (int i = tid; i < 768; i += 256) ws[i] = g_Wcat[i];
    if (tid < 6) bs[tid] = g_bcat[tid];
    __syncthreads();
    int row = blockIdx.x * 8 + (tid >> 5);
    int lane = tid & 31;
    if (row >= n) return;
    float4 a = ((const float4*)A)[row * 32 + lane];
    int k = lane * 4;
    float a0 = a.x * g_scale[k]     + g_shift[k];
    float a1 = a.y * g_scale[k + 1] + g_shift[k + 1];
    float a2 = a.z * g_scale[k + 2] + g_shift[k + 2];
    float a3 = a.w * g_scale[k + 3] + g_shift[k + 3];
    float c[6];
#pragma unroll
    for (int j = 0; j < 6; j++)
        c[j] = a0 * ws[k * 6 + j] + a1 * ws[(k + 1) * 6 + j] +
               a2 * ws[(k + 2) * 6 + j] + a3 * ws[(k + 3) * 6 + j];
#pragma unroll
    for (int j = 0; j < 6; j++)
#pragma unroll
        for (int o = 16; o > 0; o >>= 1) c[j] += __shfl_xor_sync(0xffffffffu, c[j], o);
    if (lane == 0) {
        g_HW[row * 2]     = c[0];
        g_HW[row * 2 + 1] = c[1];
        g_HL[row * 2]     = c[2] + bs[2];
        g_HL[row * 2 + 1] = c[3] + bs[3];
        g_ESD[row * 2]     = c[4];
        g_ESD[row * 2 + 1] = c[5];
    }
}

// ---------------- GAT edge phase, layers 1/2 ----------------
__device__ __forceinline__ float leaky(float x) { return (x > 0.f) ? x : LEAKY * x; }

__global__ __launch_bounds__(256) void k_gat_edge12(const float* __restrict__ gb, int n) {
    int warp = (blockIdx.x * 256 + threadIdx.x) >> 5;
    int lane = threadIdx.x & 31;
    if (warp >= n) return;
    int node = warp;
    int beg = g_off[node], end = g_off[node + 1];
    float ed0 = g_ESD[node * 4 + 2], ed1 = g_ESD[node * 4 + 3];

    float m0 = -1e30f, m1 = -1e30f;
    for (int i = beg + lane; i < end; i += 32) {
        int s = g_csr[i];
        m0 = fmaxf(m0, leaky(g_ESD[s * 4]     + ed0));
        m1 = fmaxf(m1, leaky(g_ESD[s * 4 + 1] + ed1));
    }
#pragma unroll
    for (int o = 16; o > 0; o >>= 1) {
        m0 = fmaxf(m0, __shfl_xor_sync(0xffffffffu, m0, o));
        m1 = fmaxf(m1, __shfl_xor_sync(0xffffffffu, m1, o));
    }

    float sum0 = 0.f, sum1 = 0.f;
    float ax = 0.f, ay = 0.f, az = 0.f, aw = 0.f;
    const float4* HW4 = (const float4*)g_HW;
    for (int base = beg; base < end; base += 32) {
        int i = base + lane;
        int s = 0;
        float p0 = 0.f, p1 = 0.f;
        if (i < end) {
            s = g_csr[i];
            p0 = __expf(leaky(g_ESD[s * 4]     + ed0) - m0);
            p1 = __expf(leaky(g_ESD[s * 4 + 1] + ed1) - m1);
        }
        sum0 += p0; sum1 += p1;
        int cnt = min(32, end - base);
        if (cnt == 32) {
#pragma unroll
            for (int j = 0; j < 32; j++) {
                int sj   = __shfl_sync(0xffffffffu, s, j);
                float q0 = __shfl_sync(0xffffffffu, p0, j);
                float q1 = __shfl_sync(0xffffffffu, p1, j);
                float ph = (lane < 16) ? q0 : q1;
                float4 hv = HW4[sj * 32 + lane];
                ax += ph * hv.x; ay += ph * hv.y; az += ph * hv.z; aw += ph * hv.w;
            }
        } else {
            for (int j = 0; j < cnt; j++) {
                int sj   = __shfl_sync(0xffffffffu, s, j);
                float q0 = __shfl_sync(0xffffffffu, p0, j);
                float q1 = __shfl_sync(0xffffffffu, p1, j);
                float ph = (lane < 16) ? q0 : q1;
                float4 hv = HW4[sj * 32 + lane];
                ax += ph * hv.x; ay += ph * hv.y; az += ph * hv.z; aw += ph * hv.w;
            }
        }
    }
#pragma unroll
    for (int o = 16; o > 0; o >>= 1) {
        sum0 += __shfl_xor_sync(0xffffffffu, sum0, o);
        sum1 += __shfl_xor_sync(0xffffffffu, sum1, o);
    }
    float inv = 1.f / ((lane < 16) ? sum0 : sum1);

    float4 hl = ((const float4*)g_HL)[node * 32 + lane];
    float4 gv = ((const float4*)gb)[lane];
    float4 o4;
    o4.x = fmaxf(hl.x + gv.x + ax * inv, 0.f);
    o4.y = fmaxf(hl.y + gv.y + ay * inv, 0.f);
    o4.z = fmaxf(hl.z + gv.z + az * inv, 0.f);
    o4.w = fmaxf(hl.w + gv.w + aw * inv, 0.f);
    ((float4*)g_H)[node * 32 + lane] = o4;
}

// ---------------- GAT edge phase, layer 3 ----------------
__global__ __launch_bounds__(256) void k_gat_edge3(const float* __restrict__ gb3,
                                                   float* __restrict__ out, int n) {
    int warp = (blockIdx.x * 256 + threadIdx.x) >> 5;
    int lane = threadIdx.x & 31;
    if (warp >= n) return;
    int node = warp;
    int beg = g_off[node], end = g_off[node + 1];
    float edv = g_ESD[node * 2 + 1];

    float m = -1e30f;
    for (int i = beg + lane; i < end; i += 32) {
        int s = g_csr[i];
        m = fmaxf(m, leaky(g_ESD[s * 2] + edv));
    }
#pragma unroll
    for (int o = 16; o > 0; o >>= 1) m = fmaxf(m, __shfl_xor_sync(0xffffffffu, m, o));

    float sum = 0.f, a0 = 0.f, a1 = 0.f;
    for (int i = beg + lane; i < end; i += 32) {
        int s = g_csr[i];
        float p = __expf(leaky(g_ESD[s * 2] + edv) - m);
        sum += p;
        a0 += p * g_HW[s * 2];
        a1 += p * g_HW[s * 2 + 1];
    }
#pragma unroll
    for (int o = 16; o > 0; o >>= 1) {
        sum += __shfl_xor_sync(0xffffffffu, sum, o);
        a0  += __shfl_xor_sync(0xffffffffu, a0, o);
        a1  += __shfl_xor_sync(0xffffffffu, a1, o);
    }
    if (lane == 0) {
        float inv = 1.f / sum;
        out[node * 2]     = fmaxf(g_HL[node * 2]     + gb3[0] + a0 * inv, 0.f);
        out[node * 2 + 1] = fmaxf(g_HL[node * 2 + 1] + gb3[1] + a1 * inv, 0.f);
    }
}

// ---------------- host launch ----------------
extern "C" void kernel_launch(void* const* d_in, const int* in_sizes, int n_in,
                              void* d_out, int out_size) {
    const float* x  = (const float*)d_in[0];
    const int*   ei = (const int*)d_in[1];
    const float *W1 = (const float*)d_in[2],  *as1 = (const float*)d_in[3],
                *ad1 = (const float*)d_in[4], *gb1 = (const float*)d_in[5],
                *lw1 = (const float*)d_in[6], *lb1 = (const float*)d_in[7],
                *bg1 = (const float*)d_in[8], *bb1 = (const float*)d_in[9];
    const float *W2 = (const float*)d_in[10], *as2 = (const float*)d_in[11],
                *ad2 = (const float*)d_in[12], *gb2 = (const float*)d_in[13],
                *lw2 = (const float*)d_in[14], *lb2 = (const float*)d_in[15],
                *bg2 = (const float*)d_in[16], *bb2 = (const float*)d_in[17];
    const float *W3 = (const float*)d_in[18], *as3 = (const float*)d_in[19],
                *ad3 = (const float*)d_in[20], *gb3 = (const float*)d_in[21],
                *lw3 = (const float*)d_in[22], *lb3 = (const float*)d_in[23],
                *bg3 = (const float*)d_in[24], *bb3 = (const float*)d_in[25];
    (void)n_in; (void)out_size;

    int n  = in_sizes[0] / 128;
    int E  = in_sizes[1] / 2;
    int ET = E + n;
    float* out = (float*)d_out;

    int eb = (ET + 255) / 256;
    dim3 gg((n + 127) / 128, 2);
    int wb = (n + 7) / 8;
    float inv_n = 1.f / (float)n;

    cudaFuncSetAttribute(k_gemm_mma, cudaFuncAttributeMaxDynamicSharedMemorySize, GEMM_SMEM);

    // ---- CSR build ----
    k_zero_deg<<<(SCAN_N + 255) / 256, 256>>>();
    k_count<<<eb, 256>>>(ei, E, ET);
    k_scan_bsum<<<NBLK, 256>>>();
    k_scan_top<<<1, 256>>>();
    k_scan_off<<<NBLK, 256>>>(n);
    k_scatter<<<eb, 256>>>(ei, E, ET);

    // ---- layer 1 ----
    k_bn_reduce<<<128, 256>>>(x, n * 128);
    k_bn_final<<<1, 128>>>(bg1, bb1, inv_n);
    k_prep_w12<<<(128 * 260 + 255) / 256, 256>>>(W1, lw1, lb1, as1, ad1);
    k_prep_b<<<128, 256>>>();
    k_gemm_mma<<<gg, 256, GEMM_SMEM>>>(x, n);
    k_esd<<<wb, 256>>>(x, n);
    k_gat_edge12<<<wb, 256>>>(gb1, n);

    // ---- layer 2 ----
    k_bn_reduce<<<128, 256>>>(nullptr, n * 128);
    k_bn_final<<<1, 128>>>(bg2, bb2, inv_n);
    k_prep_w12<<<(128 * 260 + 255) / 256, 256>>>(W2, lw2, lb2, as2, ad2);
    k_prep_b<<<128, 256>>>();
    k_gemm_mma<<<gg, 256, GEMM_SMEM>>>(nullptr, n);
    k_esd<<<wb, 256>>>(nullptr, n);
    k_gat_edge12<<<wb, 256>>>(gb2, n);

    // ---- layer 3 ----
    k_bn_reduce<<<128, 256>>>(nullptr, n * 128);
    k_bn_final<<<1, 128>>>(bg3, bb3, inv_n);
    k_prep_w3<<<3, 256>>>(W3, lw3, lb3, as3, ad3);
    k_gemv6<<<wb, 256>>>(n);
    k_gat_edge3<<<wb, 256>>>(gb3, out, n);
}

// round 6
// speedup vs baseline: 1.4465x; 1.1519x over previous
#include <cuda_runtime.h>
#include <cuda_bf16.h>
#include <cstdint>

#define LEAKY 0.2f
#define BN_EPS 1e-5f
#define MAXN 50000
#define MAXE 1600000
#define MAXET (MAXN + MAXE)
#define SCAN_N 50176
#define NBLK 196

// ---------------- device scratch ----------------
__device__ int   g_deg[SCAN_N];
__device__ int   g_off[MAXN + 1];
__device__ int   g_cursor[MAXN];
__device__ int   g_csr[MAXET];
__device__ int   g_bsum[256];
__device__ float g_red[256 * 256];
__device__ float g_scale[128];
__device__ float g_shift[128];
__device__ float g_Wcat[128 * 260];
__device__ float g_bcat[260];
__device__ float g_HW[MAXN * 128];
__device__ float g_HL[MAXN * 128];
__device__ float g_ESD[MAXN * 4];
__device__ float g_H[MAXN * 128];
__device__ __nv_bfloat16 g_Bhi[256 * 128];   // [n][k]
__device__ __nv_bfloat16 g_Blo[256 * 128];

#define BN_BLOCKS 148

// ---------------- CSR build ----------------
__global__ void k_zero_deg() {
    int i = blockIdx.x * 256 + threadIdx.x;
    if (i < SCAN_N) g_deg[i] = 0;
}
__global__ void k_count(const int* __restrict__ ei, int E, int ET) {
    int i = blockIdx.x * 256 + threadIdx.x;
    if (i < ET) {
        int d = (i < E) ? ei[E + i] : (i - E);
        atomicAdd(&g_deg[d], 1);
    }
}
__global__ void k_scan_bsum() {
    __shared__ int sh[256];
    int tid = threadIdx.x;
    sh[tid] = g_deg[blockIdx.x * 256 + tid];
    __syncthreads();
    for (int o = 128; o > 0; o >>= 1) {
        if (tid < o) sh[tid] += sh[tid + o];
        __syncthreads();
    }
    if (tid == 0) g_bsum[blockIdx.x] = sh[0];
}
__global__ void k_scan_top() {
    __shared__ int sh[256];
    int tid = threadIdx.x;
    int v = (tid < NBLK) ? g_bsum[tid] : 0;
    sh[tid] = v;
    __syncthreads();
    for (int o = 1; o < 256; o <<= 1) {
        int t = (tid >= o) ? sh[tid - o] : 0;
        __syncthreads();
        sh[tid] += t;
        __syncthreads();
    }
    g_bsum[tid] = sh[tid] - v;
}
__global__ void k_scan_off(int n) {
    __shared__ int sh[256];
    int tid = threadIdx.x;
    int gi = blockIdx.x * 256 + tid;
    int v = g_deg[gi];
    sh[tid] = v;
    __syncthreads();
    for (int o = 1; o < 256; o <<= 1) {
        int t = (tid >= o) ? sh[tid - o] : 0;
        __syncthreads();
        sh[tid] += t;
        __syncthreads();
    }
    int ex = sh[tid] - v + g_bsum[blockIdx.x];
    if (gi <= n) g_off[gi] = ex;
    if (gi < n)  g_cursor[gi] = ex;
}
__global__ void k_scatter(const int* __restrict__ ei, int E, int ET) {
    int i = blockIdx.x * 256 + threadIdx.x;
    if (i < ET) {
        int s, d;
        if (i < E) { s = ei[i]; d = ei[E + i]; }
        else       { s = d = i - E; }
        int pos = atomicAdd(&g_cursor[d], 1);
        g_csr[pos] = s;
    }
}

// ---------------- BatchNorm stats ----------------
__global__ __launch_bounds__(256) void k_bn_reduce(const float* __restrict__ A, int total) {
    const float* H = A ? A : g_H;
    __shared__ float ss[256], sq[256];
    int tid = threadIdx.x;
    float s = 0.f, q = 0.f;
    for (int e = blockIdx.x * 256 + tid; e < total; e += gridDim.x * 256) {
        float v = H[e];
        s += v; q += v * v;
    }
    ss[tid] = s; sq[tid] = q;
    __syncthreads();
    if (tid < 128) {
        g_red[blockIdx.x * 256 + tid]       = ss[tid] + ss[tid + 128];
        g_red[blockIdx.x * 256 + 128 + tid] = sq[tid] + sq[tid + 128];
    }
}
__device__ __forceinline__ void bn_final_body(const float* bg, const float* bb, float inv_n) {
    int c = threadIdx.x;
    if (c >= 128) return;
    float s = 0.f, q = 0.f;
    for (int b = 0; b < BN_BLOCKS; b++) {
        s += g_red[b * 256 + c];
        q += g_red[b * 256 + 128 + c];
    }
    float mu  = s * inv_n;
    float var = q * inv_n - mu * mu;
    float sc  = bg[c] * rsqrtf(var + BN_EPS);
    g_scale[c] = sc;
    g_shift[c] = bb[c] - mu * sc;
}

// ---------------- weight prep (fused: Wcat + bf16 split + bn_final) ----------------
__global__ void k_prep12(const float* __restrict__ W, const float* __restrict__ lw,
                         const float* __restrict__ lb, const float* __restrict__ as,
                         const float* __restrict__ ad,
                         const float* __restrict__ bg, const float* __restrict__ bb,
                         float inv_n) {
    if (blockIdx.x == 130) { bn_final_body(bg, bb, inv_n); return; }
    int idx = blockIdx.x * 256 + threadIdx.x;
    if (idx >= 128 * 260) return;
    int k = idx / 260, j = idx % 260;
    float v;
    if (j < 128)       v = W[k * 128 + j];
    else if (j < 256)  v = lw[k * 128 + (j - 128)];
    else {
        int t = j - 256;
        int hh = t & 1;
        const float* a = (t < 2) ? as : ad;
        float s = 0.f;
        for (int f = 0; f < 64; f++) s += W[k * 128 + hh * 64 + f] * a[hh * 64 + f];
        v = s;
    }
    g_Wcat[idx] = v;
    if (j < 256) {
        __nv_bfloat16 h = __float2bfloat16(v);
        g_Bhi[j * 128 + k] = h;
        g_Blo[j * 128 + k] = __float2bfloat16(v - __bfloat162float(h));
    }
    if (k == 0) g_bcat[j] = (j >= 128 && j < 256) ? lb[j - 128] : 0.f;
}
__global__ void k_prep3(const float* __restrict__ W3, const float* __restrict__ lw3,
                        const float* __restrict__ lb3, const float* __restrict__ as3,
                        const float* __restrict__ ad3,
                        const float* __restrict__ bg, const float* __restrict__ bb,
                        float inv_n) {
    if (blockIdx.x == 3) { bn_final_body(bg, bb, inv_n); return; }
    int idx = blockIdx.x * 256 + threadIdx.x;
    if (idx >= 128 * 6) return;
    int k = idx / 6, j = idx % 6;
    float v;
    if (j < 2)      v = W3[k * 2 + j];
    else if (j < 4) v = lw3[k * 2 + (j - 2)];
    else {
        const float* a = (j == 4) ? as3 : ad3;
        v = W3[k * 2] * a[0] + W3[k * 2 + 1] * a[1];
    }
    g_Wcat[idx] = v;
    if (k == 0) g_bcat[j] = (j == 2 || j == 3) ? lb3[j - 2] : 0.f;
}

// ---------------- mma.sync GEMM helpers ----------------
__device__ __forceinline__ uint32_t smem_u32(const void* p) {
    uint32_t a;
    asm("{ .reg .u64 t; cvta.to.shared.u64 t, %1; cvt.u32.u64 %0, t; }" : "=r"(a) : "l"(p));
    return a;
}
__device__ __forceinline__ void ldsm_x4(uint32_t* r, uint32_t addr) {
    asm volatile("ldmatrix.sync.aligned.m8n8.x4.shared.b16 {%0,%1,%2,%3}, [%4];"
        : "=r"(r[0]), "=r"(r[1]), "=r"(r[2]), "=r"(r[3]) : "r"(addr));
}
__device__ __forceinline__ void ldsm_x2(uint32_t* r, uint32_t addr) {
    asm volatile("ldmatrix.sync.aligned.m8n8.x2.shared.b16 {%0,%1}, [%2];"
        : "=r"(r[0]), "=r"(r[1]) : "r"(addr));
}
__device__ __forceinline__ void mma_bf16(float* d, const uint32_t* a, const uint32_t* b) {
    asm volatile("mma.sync.aligned.m16n8k16.row.col.f32.bf16.bf16.f32 "
        "{%0,%1,%2,%3}, {%4,%5,%6,%7}, {%8,%9}, {%0,%1,%2,%3};"
        : "+f"(d[0]), "+f"(d[1]), "+f"(d[2]), "+f"(d[3])
        : "r"(a[0]), "r"(a[1]), "r"(a[2]), "r"(a[3]), "r"(b[0]), "r"(b[1]));
}

// ---------------- tensor-core GEMM + fused esd ----------------
#define APAD 136
#define TILE_BYTES (128 * APAD * 2)
#define GEMM_SMEM  (4 * TILE_BYTES + 2048)

__global__ __launch_bounds__(256, 1) void k_gemm_mma(const float* __restrict__ Ain, int M) {
    const float* A = Ain ? Ain : g_H;
    extern __shared__ char sm[];
    __nv_bfloat16* sAhi = (__nv_bfloat16*)sm;
    __nv_bfloat16* sAlo = (__nv_bfloat16*)(sm + TILE_BYTES);
    __nv_bfloat16* sBhi = (__nv_bfloat16*)(sm + 2 * TILE_BYTES);
    __nv_bfloat16* sBlo = (__nv_bfloat16*)(sm + 3 * TILE_BYTES);
    float* wesd = (float*)(sm + 4 * TILE_BYTES);   // [k][4]

    int tid = threadIdx.x, lane = tid & 31, wid = tid >> 5;
    int warp_m = wid & 1;
    int warp_n = wid >> 1;
    int m0 = blockIdx.x * 128;
    int n0 = blockIdx.y * 128;

    // ---- stage A (bn + hi/lo split) ----
    for (int idx = tid; idx < 4096; idx += 256) {
        int row = idx >> 5, c = (idx & 31) * 4;
        int gm = m0 + row;
        float4 t = (gm < M) ? *(const float4*)(A + gm * 128 + c)
                            : make_float4(0.f, 0.f, 0.f, 0.f);
        float v0 = t.x * g_scale[c]     + g_shift[c];
        float v1 = t.y * g_scale[c + 1] + g_shift[c + 1];
        float v2 = t.z * g_scale[c + 2] + g_shift[c + 2];
        float v3 = t.w * g_scale[c + 3] + g_shift[c + 3];
        if (gm >= M) { v0 = v1 = v2 = v3 = 0.f; }
        __nv_bfloat16 h0 = __float2bfloat16(v0), h1 = __float2bfloat16(v1);
        __nv_bfloat16 h2 = __float2bfloat16(v2), h3 = __float2bfloat16(v3);
        __nv_bfloat162 hp0(h0, h1), hp1(h2, h3);
        __nv_bfloat162 lp0(__float2bfloat16(v0 - __bfloat162float(h0)),
                           __float2bfloat16(v1 - __bfloat162float(h1)));
        __nv_bfloat162 lp1(__float2bfloat16(v2 - __bfloat162float(h2)),
                           __float2bfloat16(v3 - __bfloat162float(h3)));
        int o = row * APAD + c;
        *(__nv_bfloat162*)(sAhi + o)     = hp0;
        *(__nv_bfloat162*)(sAhi + o + 2) = hp1;
        *(__nv_bfloat162*)(sAlo + o)     = lp0;
        *(__nv_bfloat162*)(sAlo + o + 2) = lp1;
    }
    // ---- stage B (pre-split, [n][k]) ----
    for (int idx = tid; idx < 2048; idx += 256) {
        int row = idx >> 4, c = (idx & 15) * 8;
        int gn = n0 + row;
        uint4 hv = *(const uint4*)(g_Bhi + gn * 128 + c);
        uint4 lv = *(const uint4*)(g_Blo + gn * 128 + c);
        int o = row * APAD + c;
        *(uint4*)(sBhi + o) = hv;
        *(uint4*)(sBlo + o) = lv;
    }
    if (blockIdx.y == 1)
        for (int i = tid; i < 512; i += 256)
            wesd[i] = g_Wcat[(i >> 2) * 260 + 256 + (i & 3)];
    __syncthreads();

    int rA = lane & 15, cA = (lane >> 4) * 8;
    int rB = lane & 7,  cB = ((lane >> 3) & 1) * 8;
    uint32_t baseAhi[4], baseAlo[4], baseBhi[4], baseBlo[4];
#pragma unroll
    for (int mt = 0; mt < 4; mt++) {
        int row = warp_m * 64 + mt * 16 + rA;
        baseAhi[mt] = smem_u32(sAhi + row * APAD + cA);
        baseAlo[mt] = smem_u32(sAlo + row * APAD + cA);
    }
#pragma unroll
    for (int nt = 0; nt < 4; nt++) {
        int row = warp_n * 32 + nt * 8 + rB;
        baseBhi[nt] = smem_u32(sBhi + row * APAD + cB);
        baseBlo[nt] = smem_u32(sBlo + row * APAD + cB);
    }

    float acc[4][4][4] = {};
#pragma unroll
    for (int ks = 0; ks < 8; ks++) {
        uint32_t koff = ks * 32;
        uint32_t ahi[4][4], alo[4][4], bhi[4][2], blo[4][2];
#pragma unroll
        for (int mt = 0; mt < 4; mt++) {
            ldsm_x4(ahi[mt], baseAhi[mt] + koff);
            ldsm_x4(alo[mt], baseAlo[mt] + koff);
        }
#pragma unroll
        for (int nt = 0; nt < 4; nt++) {
            ldsm_x2(bhi[nt], baseBhi[nt] + koff);
            ldsm_x2(blo[nt], baseBlo[nt] + koff);
        }
#pragma unroll
        for (int mt = 0; mt < 4; mt++)
#pragma unroll
            for (int nt = 0; nt < 4; nt++) {
                mma_bf16(acc[mt][nt], ahi[mt], bhi[nt]);
                mma_bf16(acc[mt][nt], ahi[mt], blo[nt]);
                mma_bf16(acc[mt][nt], alo[mt], bhi[nt]);
            }
    }

    // ---- epilogue: bias + scatter ----
    float* dst = (blockIdx.y == 0) ? g_HW : g_HL;
#pragma unroll
    for (int mt = 0; mt < 4; mt++) {
        int gm0 = m0 + warp_m * 64 + mt * 16 + (lane >> 2);
#pragma unroll
        for (int nt = 0; nt < 4; nt++) {
            int col = warp_n * 32 + nt * 8 + (lane & 3) * 2;
            float b0 = g_bcat[n0 + col], b1 = g_bcat[n0 + col + 1];
            if (gm0 < M) {
                float2 v = {acc[mt][nt][0] + b0, acc[mt][nt][1] + b1};
                *(float2*)(dst + gm0 * 128 + col) = v;
            }
            if (gm0 + 8 < M) {
                float2 v = {acc[mt][nt][2] + b0, acc[mt][nt][3] + b1};
                *(float2*)(dst + (gm0 + 8) * 128 + col) = v;
            }
        }
    }

    // ---- fused esd: 4 attention columns from staged bn(A) ----
    if (blockIdx.y == 1) {
        for (int r = 0; r < 16; r++) {
            int row = wid * 16 + r;
            int gm = m0 + row;
            int k = lane * 4;
            int o = row * APAD + k;
            float a0 = __bfloat162float(sAhi[o])     + __bfloat162float(sAlo[o]);
            float a1 = __bfloat162float(sAhi[o + 1]) + __bfloat162float(sAlo[o + 1]);
            float a2 = __bfloat162float(sAhi[o + 2]) + __bfloat162float(sAlo[o + 2]);
            float a3 = __bfloat162float(sAhi[o + 3]) + __bfloat162float(sAlo[o + 3]);
            float s0 = a0 * wesd[k * 4]     + a1 * wesd[(k + 1) * 4]     + a2 * wesd[(k + 2) * 4]     + a3 * wesd[(k + 3) * 4];
            float s1 = a0 * wesd[k * 4 + 1] + a1 * wesd[(k + 1) * 4 + 1] + a2 * wesd[(k + 2) * 4 + 1] + a3 * wesd[(k + 3) * 4 + 1];
            float s2 = a0 * wesd[k * 4 + 2] + a1 * wesd[(k + 1) * 4 + 2] + a2 * wesd[(k + 2) * 4 + 2] + a3 * wesd[(k + 3) * 4 + 2];
            float s3 = a0 * wesd[k * 4 + 3] + a1 * wesd[(k + 1) * 4 + 3] + a2 * wesd[(k + 2) * 4 + 3] + a3 * wesd[(k + 3) * 4 + 3];
#pragma unroll
            for (int sh = 16; sh > 0; sh >>= 1) {
                s0 += __shfl_xor_sync(0xffffffffu, s0, sh);
                s1 += __shfl_xor_sync(0xffffffffu, s1, sh);
                s2 += __shfl_xor_sync(0xffffffffu, s2, sh);
                s3 += __shfl_xor_sync(0xffffffffu, s3, sh);
            }
            if (lane == 0 && gm < M) {
                float4 v = {s0, s1, s2, s3};
                ((float4*)g_ESD)[gm] = v;
            }
        }
    }
}

// ---------------- skinny GEMV for layer 3 ----------------
__global__ __launch_bounds__(256) void k_gemv6(int n) {
    const float* A = g_H;
    __shared__ float ws[128 * 6];
    __shared__ float bs[6];
    int tid = threadIdx.x;
    for (int i = tid; i < 768; i += 256) ws[i] = g_Wcat[i];
    if (tid < 6) bs[tid] = g_bcat[tid];
    __syncthreads();
    int row = blockIdx.x * 8 + (tid >> 5);
    int lane = tid & 31;
    if (row >= n) return;
    float4 a = ((const float4*)A)[row * 32 + lane];
    int k = lane * 4;
    float a0 = a.x * g_scale[k]     + g_shift[k];
    float a1 = a.y * g_scale[k + 1] + g_shift[k + 1];
    float a2 = a.z * g_scale[k + 2] + g_shift[k + 2];
    float a3 = a.w * g_scale[k + 3] + g_shift[k + 3];
    float c[6];
#pragma unroll
    for (int j = 0; j < 6; j++)
        c[j] = a0 * ws[k * 6 + j] + a1 * ws[(k + 1) * 6 + j] +
               a2 * ws[(k + 2) * 6 + j] + a3 * ws[(k + 3) * 6 + j];
#pragma unroll
    for (int j = 0; j < 6; j++)
#pragma unroll
        for (int o = 16; o > 0; o >>= 1) c[j] += __shfl_xor_sync(0xffffffffu, c[j], o);
    if (lane == 0) {
        g_HW[row * 2]     = c[0];
        g_HW[row * 2 + 1] = c[1];
        g_HL[row * 2]     = c[2] + bs[2];
        g_HL[row * 2 + 1] = c[3] + bs[3];
        g_ESD[row * 2]     = c[4];
        g_ESD[row * 2 + 1] = c[5];
    }
}

// ---------------- GAT edge phase, layers 1/2 ----------------
__device__ __forceinline__ float leaky(float x) { return (x > 0.f) ? x : LEAKY * x; }

__global__ __launch_bounds__(256) void k_gat_edge12(const float* __restrict__ gb, int n) {
    int warp = (blockIdx.x * 256 + threadIdx.x) >> 5;
    int lane = threadIdx.x & 31;
    if (warp >= n) return;
    int node = warp;
    int beg = g_off[node], end = g_off[node + 1];
    float ed0 = g_ESD[node * 4 + 2], ed1 = g_ESD[node * 4 + 3];
    const float4* ESD4 = (const float4*)g_ESD;

    float m0 = -1e30f, m1 = -1e30f;
    for (int i = beg + lane; i < end; i += 32) {
        int s = g_csr[i];
        float4 e = ESD4[s];
        m0 = fmaxf(m0, leaky(e.x + ed0));
        m1 = fmaxf(m1, leaky(e.y + ed1));
    }
#pragma unroll
    for (int o = 16; o > 0; o >>= 1) {
        m0 = fmaxf(m0, __shfl_xor_sync(0xffffffffu, m0, o));
        m1 = fmaxf(m1, __shfl_xor_sync(0xffffffffu, m1, o));
    }

    float sum0 = 0.f, sum1 = 0.f;
    float ax = 0.f, ay = 0.f, az = 0.f, aw = 0.f;
    const float4* HW4 = (const float4*)g_HW;
    for (int base = beg; base < end; base += 32) {
        int i = base + lane;
        int s = 0;
        float p0 = 0.f, p1 = 0.f;
        if (i < end) {
            s = g_csr[i];
            float4 e = ESD4[s];
            p0 = __expf(leaky(e.x + ed0) - m0);
            p1 = __expf(leaky(e.y + ed1) - m1);
        }
        sum0 += p0; sum1 += p1;
        int cnt = min(32, end - base);
        if (cnt == 32) {
#pragma unroll
            for (int j = 0; j < 32; j++) {
                int sj   = __shfl_sync(0xffffffffu, s, j);
                float q0 = __shfl_sync(0xffffffffu, p0, j);
                float q1 = __shfl_sync(0xffffffffu, p1, j);
                float ph = (lane < 16) ? q0 : q1;
                float4 hv = HW4[sj * 32 + lane];
                ax += ph * hv.x; ay += ph * hv.y; az += ph * hv.z; aw += ph * hv.w;
            }
        } else {
            for (int j = 0; j < cnt; j++) {
                int sj   = __shfl_sync(0xffffffffu, s, j);
                float q0 = __shfl_sync(0xffffffffu, p0, j);
                float q1 = __shfl_sync(0xffffffffu, p1, j);
                float ph = (lane < 16) ? q0 : q1;
                float4 hv = HW4[sj * 32 + lane];
                ax += ph * hv.x; ay += ph * hv.y; az += ph * hv.z; aw += ph * hv.w;
            }
        }
    }
#pragma unroll
    for (int o = 16; o > 0; o >>= 1) {
        sum0 += __shfl_xor_sync(0xffffffffu, sum0, o);
        sum1 += __shfl_xor_sync(0xffffffffu, sum1, o);
    }
    float inv = 1.f / ((lane < 16) ? sum0 : sum1);

    float4 hl = ((const float4*)g_HL)[node * 32 + lane];
    float4 gv = ((const float4*)gb)[lane];
    float4 o4;
    o4.x = fmaxf(hl.x + gv.x + ax * inv, 0.f);
    o4.y = fmaxf(hl.y + gv.y + ay * inv, 0.f);
    o4.z = fmaxf(hl.z + gv.z + az * inv, 0.f);
    o4.w = fmaxf(hl.w + gv.w + aw * inv, 0.f);
    ((float4*)g_H)[node * 32 + lane] = o4;
}

// ---------------- GAT edge phase, layer 3 ----------------
__global__ __launch_bounds__(256) void k_gat_edge3(const float* __restrict__ gb3,
                                                   float* __restrict__ out, int n) {
    int warp = (blockIdx.x * 256 + threadIdx.x) >> 5;
    int lane = threadIdx.x & 31;
    if (warp >= n) return;
    int node = warp;
    int beg = g_off[node], end = g_off[node + 1];
    float edv = g_ESD[node * 2 + 1];
    const float2* ESD2 = (const float2*)g_ESD;
    const float2* HW2 = (const float2*)g_HW;

    float m = -1e30f;
    for (int i = beg + lane; i < end; i += 32) {
        int s = g_csr[i];
        m = fmaxf(m, leaky(ESD2[s].x + edv));
    }
#pragma unroll
    for (int o = 16; o > 0; o >>= 1) m = fmaxf(m, __shfl_xor_sync(0xffffffffu, m, o));

    float sum = 0.f, a0 = 0.f, a1 = 0.f;
    for (int i = beg + lane; i < end; i += 32) {
        int s = g_csr[i];
        float p = __expf(leaky(ESD2[s].x + edv) - m);
        float2 h = HW2[s];
        sum += p;
        a0 += p * h.x;
        a1 += p * h.y;
    }
#pragma unroll
    for (int o = 16; o > 0; o >>= 1) {
        sum += __shfl_xor_sync(0xffffffffu, sum, o);
        a0  += __shfl_xor_sync(0xffffffffu, a0, o);
        a1  += __shfl_xor_sync(0xffffffffu, a1, o);
    }
    if (lane == 0) {
        float inv = 1.f / sum;
        out[node * 2]     = fmaxf(g_HL[node * 2]     + gb3[0] + a0 * inv, 0.f);
        out[node * 2 + 1] = fmaxf(g_HL[node * 2 + 1] + gb3[1] + a1 * inv, 0.f);
    }
}

// ---------------- host launch ----------------
extern "C" void kernel_launch(void* const* d_in, const int* in_sizes, int n_in,
                              void* d_out, int out_size) {
    const float* x  = (const float*)d_in[0];
    const int*   ei = (const int*)d_in[1];
    const float *W1 = (const float*)d_in[2],  *as1 = (const float*)d_in[3],
                *ad1 = (const float*)d_in[4], *gb1 = (const float*)d_in[5],
                *lw1 = (const float*)d_in[6], *lb1 = (const float*)d_in[7],
                *bg1 = (const float*)d_in[8], *bb1 = (const float*)d_in[9];
    const float *W2 = (const float*)d_in[10], *as2 = (const float*)d_in[11],
                *ad2 = (const float*)d_in[12], *gb2 = (const float*)d_in[13],
                *lw2 = (const float*)d_in[14], *lb2 = (const float*)d_in[15],
                *bg2 = (const float*)d_in[16], *bb2 = (const float*)d_in[17];
    const float *W3 = (const float*)d_in[18], *as3 = (const float*)d_in[19],
                *ad3 = (const float*)d_in[20], *gb3 = (const float*)d_in[21],
                *lw3 = (const float*)d_in[22], *lb3 = (const float*)d_in[23],
                *bg3 = (const float*)d_in[24], *bb3 = (const float*)d_in[25];
    (void)n_in; (void)out_size;

    int n  = in_sizes[0] / 128;
    int E  = in_sizes[1] / 2;
    int ET = E + n;
    float* out = (float*)d_out;

    int eb = (ET + 255) / 256;
    dim3 gg((n + 127) / 128, 2);
    int wb = (n + 7) / 8;
    float inv_n = 1.f / (float)n;

    cudaFuncSetAttribute(k_gemm_mma, cudaFuncAttributeMaxDynamicSharedMemorySize, GEMM_SMEM);

    // lazily-created side stream + events (setup only; identical work every call)
    static cudaStream_t s_side = nullptr;
    static cudaEvent_t ev_fork = nullptr, ev_join = nullptr;
    if (!s_side) {
        cudaStreamCreateWithFlags(&s_side, cudaStreamNonBlocking);
        cudaEventCreateWithFlags(&ev_fork, cudaEventDisableTiming);
        cudaEventCreateWithFlags(&ev_join, cudaEventDisableTiming);
    }

    // ---- fork: CSR build on side stream, overlapped with layer-1 BN/prep/GEMM ----
    cudaEventRecord(ev_fork, 0);
    cudaStreamWaitEvent(s_side, ev_fork, 0);
    k_zero_deg<<<(SCAN_N + 255) / 256, 256, 0, s_side>>>();
    k_count<<<eb, 256, 0, s_side>>>(ei, E, ET);
    k_scan_bsum<<<NBLK, 256, 0, s_side>>>();
    k_scan_top<<<1, 256, 0, s_side>>>();
    k_scan_off<<<NBLK, 256, 0, s_side>>>(n);
    k_scatter<<<eb, 256, 0, s_side>>>(ei, E, ET);
    cudaEventRecord(ev_join, s_side);

    // ---- layer 1 (main stream) ----
    k_bn_reduce<<<BN_BLOCKS, 256>>>(x, n * 128);
    k_prep12<<<131, 256>>>(W1, lw1, lb1, as1, ad1, bg1, bb1, inv_n);
    k_gemm_mma<<<gg, 256, GEMM_SMEM>>>(x, n);
    cudaStreamWaitEvent(0, ev_join, 0);
    k_gat_edge12<<<wb, 256>>>(gb1, n);

    // ---- layer 2 ----
    k_bn_reduce<<<BN_BLOCKS, 256>>>(nullptr, n * 128);
    k_prep12<<<131, 256>>>(W2, lw2, lb2, as2, ad2, bg2, bb2, inv_n);
    k_gemm_mma<<<gg, 256, GEMM_SMEM>>>(nullptr, n);
    k_gat_edge12<<<wb, 256>>>(gb2, n);

    // ---- layer 3 ----
    k_bn_reduce<<<BN_BLOCKS, 256>>>(nullptr, n * 128);
    k_prep3<<<4, 256>>>(W3, lw3, lb3, as3, ad3, bg3, bb3, inv_n);
    k_gemv6<<<wb, 256>>>(n);
    k_gat_edge3<<<wb, 256>>>(gb3, out, n);
}